// round 11
// baseline (speedup 1.0000x reference)
#include <cuda_runtime.h>
#include <cuda_bf16.h>
#include <mma.h>
#include <cstdint>

using namespace nvcuda;

// ---------------- Problem constants ----------------
#define BATCH     2
#define SEQLEN    1024
#define TOK       (BATCH*SEQLEN)        // 2048
#define D_MODEL   1024
#define D_INNER   2048
#define NHEADS    32
#define HEADDIM   64
#define D_STATE   128
#define D_CONV    4
#define CONV_DIM  (D_INNER + 2*D_STATE)            // 2304
#define D_IN_PROJ (2*D_INNER + 2*D_STATE + NHEADS) // 4384
#define INTER     2752
#define EPS       1e-6f

// ---------------- Scratch (device globals) ----------------
__device__ float g_h     [TOK * D_MODEL];
__device__ float g_zx    [TOK * D_IN_PROJ];
__device__ float g_xbc   [TOK * CONV_DIM];
__device__ float g_dt    [TOK * NHEADS];
__device__ float g_y     [TOK * D_INNER];
__device__ float g_yn    [TOK * D_INNER];
__device__ float g_x1    [TOK * D_MODEL];
__device__ float g_h2    [TOK * D_MODEL];
__device__ float g_gate  [TOK * INTER];
__device__ float g_up    [TOK * INTER];
__device__ float g_inter [TOK * INTER];

// ---------------- cp.async helpers ----------------
__device__ __forceinline__ void cp_async16(void* smem, const void* gmem, bool pred) {
    unsigned int s = (unsigned int)__cvta_generic_to_shared(smem);
    int sz = pred ? 16 : 0;
    asm volatile("cp.async.cg.shared.global [%0], [%1], 16, %2;\n"
                 :: "r"(s), "l"(gmem), "r"(sz));
}
__device__ __forceinline__ void cp_commit() {
    asm volatile("cp.async.commit_group;\n");
}
template<int N> __device__ __forceinline__ void cp_wait() {
    asm volatile("cp.async.wait_group %0;\n" :: "n"(N));
}

// ---------------- RMSNorm ----------------
__global__ void rmsnorm_kernel(const float* __restrict__ x, const float* __restrict__ w,
                               float* __restrict__ o, int cols) {
    int row = blockIdx.x;
    const float* xr = x + (long)row * cols;
    float*       orr = o + (long)row * cols;
    float s = 0.f;
    for (int c = threadIdx.x; c < cols; c += blockDim.x) { float v = xr[c]; s += v * v; }
    __shared__ float red[256];
    red[threadIdx.x] = s; __syncthreads();
    for (int st = 128; st > 0; st >>= 1) {
        if (threadIdx.x < st) red[threadIdx.x] += red[threadIdx.x + st];
        __syncthreads();
    }
    float scale = rsqrtf(red[0] / (float)cols + EPS);
    for (int c = threadIdx.x; c < cols; c += blockDim.x) orr[c] = xr[c] * scale * w[c];
}

// ---------------- TF32 tensor-core GEMM (pipelined): C = A[M,K] @ B[N,K]^T (+res) ------
// CTA tile 128x128, BK=16, 3-stage cp.async pipeline, 256 threads = 8 warps.
// Warp tile 64x32: warps arranged 2 (M) x 4 (N). Requires M%128==0, K%16==0.
#define BM 128
#define BN 128
#define BKT 16
#define STG 3
#define SPAD 20                      // smem row stride (floats)
#define ST_SZ (BM * SPAD)            // floats per A stage (B same)

__global__ __launch_bounds__(256)
void gemm_tf32(const float* __restrict__ A, const float* __restrict__ B,
               const float* __restrict__ res, float* __restrict__ C,
               int M, int N, int K) {
    extern __shared__ __align__(16) float sm[];   // [STG*ST_SZ] A | [STG*ST_SZ] B
    float* As = sm;
    float* Bs = sm + STG * ST_SZ;

    int tid  = threadIdx.x;
    int lane = tid & 31;
    int wid  = tid >> 5;
    int wm   = wid & 1;              // 0..1 -> 64 rows
    int wn   = wid >> 1;             // 0..3 -> 32 cols
    int m0 = blockIdx.y * BM, n0 = blockIdx.x * BN;

    wmma::fragment<wmma::accumulator, 16, 16, 8, float> acc[4][2];
#pragma unroll
    for (int i = 0; i < 4; i++)
#pragma unroll
        for (int j = 0; j < 2; j++) wmma::fill_fragment(acc[i][j], 0.f);

    // global load mapping: lr in 0..63, rows lr and lr+64; 16B per thread per row
    int lr = tid >> 2;
    int lc = (tid & 3) * 4;
    const float* Aptr0 = A + (long)(m0 + lr) * K + lc;
    const float* Aptr1 = Aptr0 + (long)64 * K;
    int nB0 = n0 + lr, nB1 = n0 + lr + 64;
    bool bok0 = nB0 < N, bok1 = nB1 < N;
    const float* Bptr0 = bok0 ? (B + (long)nB0 * K + lc) : B;
    const float* Bptr1 = bok1 ? (B + (long)nB1 * K + lc) : B;
    int sOff0 = lr * SPAD + lc;
    int sOff1 = (lr + 64) * SPAD + lc;

    int nk = K / BKT;

    // prologue: stages 0..STG-2
#pragma unroll
    for (int s = 0; s < STG - 1; s++) {
        int koff = s * BKT;
        float* Aw = As + s * ST_SZ;
        float* Bw = Bs + s * ST_SZ;
        cp_async16(Aw + sOff0, Aptr0 + koff, true);
        cp_async16(Aw + sOff1, Aptr1 + koff, true);
        cp_async16(Bw + sOff0, Bptr0 + (bok0 ? koff : 0), bok0);
        cp_async16(Bw + sOff1, Bptr1 + (bok1 ? koff : 0), bok1);
        cp_commit();
    }
    cp_wait<STG - 2>();
    __syncthreads();

    for (int kt = 0; kt < nk; kt++) {
        int slot = kt % STG;
        // issue load for stage kt+STG-1
        int pf = kt + STG - 1;
        if (pf < nk) {
            int koff = pf * BKT;
            int ps = pf % STG;
            float* Aw = As + ps * ST_SZ;
            float* Bw = Bs + ps * ST_SZ;
            cp_async16(Aw + sOff0, Aptr0 + koff, true);
            cp_async16(Aw + sOff1, Aptr1 + koff, true);
            cp_async16(Bw + sOff0, Bptr0 + (bok0 ? koff : 0), bok0);
            cp_async16(Bw + sOff1, Bptr1 + (bok1 ? koff : 0), bok1);
        }
        cp_commit();

        const float* Ac = As + slot * ST_SZ;
        const float* Bc = Bs + slot * ST_SZ;
#pragma unroll
        for (int ks = 0; ks < BKT; ks += 8) {
            wmma::fragment<wmma::matrix_a, 16, 16, 8, wmma::precision::tf32, wmma::row_major> af[4];
            wmma::fragment<wmma::matrix_b, 16, 16, 8, wmma::precision::tf32, wmma::col_major> bf[2];
#pragma unroll
            for (int i = 0; i < 4; i++) {
                wmma::load_matrix_sync(af[i], Ac + (wm * 64 + i * 16) * SPAD + ks, SPAD);
#pragma unroll
                for (int t = 0; t < af[i].num_elements; t++)
                    af[i].x[t] = wmma::__float_to_tf32(af[i].x[t]);
            }
#pragma unroll
            for (int j = 0; j < 2; j++) {
                wmma::load_matrix_sync(bf[j], Bc + (wn * 32 + j * 16) * SPAD + ks, SPAD);
#pragma unroll
                for (int t = 0; t < bf[j].num_elements; t++)
                    bf[j].x[t] = wmma::__float_to_tf32(bf[j].x[t]);
            }
#pragma unroll
            for (int i = 0; i < 4; i++)
#pragma unroll
                for (int j = 0; j < 2; j++)
                    wmma::mma_sync(acc[i][j], af[i], bf[j], acc[i][j]);
        }
        cp_wait<STG - 2>();
        __syncthreads();
    }

    // ---------------- Epilogue ----------------
    if (n0 + BN <= N) {
        // full tile: store fragments directly to global (residual via frag load)
#pragma unroll
        for (int i = 0; i < 4; i++)
#pragma unroll
            for (int j = 0; j < 2; j++) {
                long goff = (long)(m0 + wm * 64 + i * 16) * N + n0 + wn * 32 + j * 16;
                if (res) {
                    wmma::fragment<wmma::accumulator, 16, 16, 8, float> cf;
                    wmma::load_matrix_sync(cf, res + goff, N, wmma::mem_row_major);
#pragma unroll
                    for (int t = 0; t < cf.num_elements; t++) acc[i][j].x[t] += cf.x[t];
                }
                wmma::store_matrix_sync(C + goff, acc[i][j], N, wmma::mem_row_major);
            }
    } else {
        // partial N tile: stage each 16x16 frag through per-warp smem, guarded copy
        __syncthreads();                     // smem free for reuse
        float* buf = sm + wid * 320;         // 16 x 20
#pragma unroll
        for (int i = 0; i < 4; i++)
#pragma unroll
            for (int j = 0; j < 2; j++) {
                wmma::store_matrix_sync(buf, acc[i][j], 20, wmma::mem_row_major);
                __syncwarp();
                int nbase = n0 + wn * 32 + j * 16;
                int mbase = m0 + wm * 64 + i * 16;
#pragma unroll
                for (int e = lane; e < 256; e += 32) {
                    int r = e >> 4, cc = e & 15;
                    int gn = nbase + cc;
                    if (gn < N) {
                        long gi = (long)(mbase + r) * N + gn;
                        float v = buf[r * 20 + cc];
                        if (res) v += res[gi];
                        C[gi] = v;
                    }
                }
                __syncwarp();
            }
    }
}

// ---------------- Causal depthwise conv (width 4) + SiLU ----------------
__global__ void conv_silu_kernel(const float* __restrict__ zx,
                                 const float* __restrict__ cw,
                                 const float* __restrict__ cb,
                                 float* __restrict__ xbc) {
    long idx = (long)blockIdx.x * blockDim.x + threadIdx.x;
    if (idx >= (long)TOK * CONV_DIM) return;
    int c = (int)(idx % CONV_DIM);
    int row = (int)(idx / CONV_DIM);
    int l = row & (SEQLEN - 1);
    int b = row >> 10;
    float v = cb[c];
#pragma unroll
    for (int k = 0; k < D_CONV; k++) {
        int li = l - (D_CONV - 1) + k;
        if (li >= 0)
            v += zx[((long)(b * SEQLEN + li)) * D_IN_PROJ + D_INNER + c] * cw[c * D_CONV + k];
    }
    xbc[idx] = v / (1.f + expf(-v));
}

// ---------------- dt softplus ----------------
__global__ void dt_softplus_kernel(const float* __restrict__ zx,
                                   const float* __restrict__ dt_bias,
                                   float* __restrict__ dtb) {
    int idx = blockIdx.x * blockDim.x + threadIdx.x;
    if (idx >= TOK * NHEADS) return;
    int h = idx & (NHEADS - 1);
    int row = idx >> 5;
    float x = zx[(long)row * D_IN_PROJ + (D_IN_PROJ - NHEADS) + h] + dt_bias[h];
    dtb[idx] = (x > 20.f) ? x : log1pf(expf(x));
}

// ---------------- SSM selective scan: one CTA per (batch, head), 256 threads ----------
__global__ __launch_bounds__(256, 1)
void scan_kernel(const float* __restrict__ xbc,
                 const float* __restrict__ dtb,
                 const float* __restrict__ A_log,
                 const float* __restrict__ Dp,
                 float* __restrict__ y) {
    int b  = blockIdx.x >> 5;
    int hh = blockIdx.x & 31;
    int tid = threadIdx.x;
    int p = tid >> 2;
    int q = tid & 3;
    int nb = q * 32;
    float A  = -expf(A_log[hh]);
    float Dh = Dp[hh];

    __shared__ float sdt[SEQLEN];
    __shared__ float sdA[SEQLEN];
    __shared__ __align__(16) float sBC[2][256];
    __shared__ __align__(16) float sx[2][64];

    for (int t = tid; t < SEQLEN; t += 256) {
        float dt = dtb[(b * SEQLEN + t) * NHEADS + hh];
        sdt[t] = dt;
        sdA[t] = expf(dt * A);
    }
    {
        const float* base0 = xbc + (long)(b * SEQLEN) * CONV_DIM;
        if (tid < 64)
            ((float4*)sBC[0])[tid] = ((const float4*)(base0 + D_INNER))[tid];
        else if (tid < 80)
            ((float4*)sx[0])[tid - 64] = ((const float4*)(base0 + hh * HEADDIM))[tid - 64];
    }
    __syncthreads();

    float hst[32];
#pragma unroll
    for (int i = 0; i < 32; i++) hst[i] = 0.f;

    for (int t = 0; t < SEQLEN; t++) {
        int cur = t & 1, nxt = cur ^ 1;
        if (t + 1 < SEQLEN) {
            const float* baseN = xbc + (long)(b * SEQLEN + t + 1) * CONV_DIM;
            if (tid < 64)
                ((float4*)sBC[nxt])[tid] = ((const float4*)(baseN + D_INNER))[tid];
            else if (tid < 80)
                ((float4*)sx[nxt])[tid - 64] = ((const float4*)(baseN + hh * HEADDIM))[tid - 64];
        }
        float dt = sdt[t], dA = sdA[t];
        float xp = sx[cur][p];
        float coef = dt * xp;
        float acc = 0.f;
        const float4* B4 = (const float4*)(sBC[cur] + nb);
        const float4* C4 = (const float4*)(sBC[cur] + 128 + nb);
#pragma unroll
        for (int i = 0; i < 8; i++) {
            int i2 = (i + 2 * q) & 7;
            float4 bb = B4[i2];
            float4 cc = C4[i2];
            int s = i2 * 4;
            hst[s+0] = hst[s+0] * dA + coef * bb.x; acc += hst[s+0] * cc.x;
            hst[s+1] = hst[s+1] * dA + coef * bb.y; acc += hst[s+1] * cc.y;
            hst[s+2] = hst[s+2] * dA + coef * bb.z; acc += hst[s+2] * cc.z;
            hst[s+3] = hst[s+3] * dA + coef * bb.w; acc += hst[s+3] * cc.w;
        }
        acc += __shfl_xor_sync(0xffffffffu, acc, 1);
        acc += __shfl_xor_sync(0xffffffffu, acc, 2);
        if (q == 0)
            y[(long)(b * SEQLEN + t) * D_INNER + hh * HEADDIM + p] = acc + Dh * xp;
        __syncthreads();
    }
}

// ---------------- Gated RMSNorm: rmsnorm(y * silu(z)) * w ----------------
__global__ void gated_rmsnorm_kernel(const float* __restrict__ y,
                                     const float* __restrict__ zx,
                                     const float* __restrict__ w,
                                     float* __restrict__ o) {
    int row = blockIdx.x;
    const float* yr = y  + (long)row * D_INNER;
    const float* zr = zx + (long)row * D_IN_PROJ;
    float*       orr = o + (long)row * D_INNER;
    __shared__ float vbuf[D_INNER];
    __shared__ float red[256];
    float s = 0.f;
    for (int c = threadIdx.x; c < D_INNER; c += blockDim.x) {
        float z = zr[c];
        float v = yr[c] * (z / (1.f + expf(-z)));
        vbuf[c] = v;
        s += v * v;
    }
    red[threadIdx.x] = s; __syncthreads();
    for (int st = 128; st > 0; st >>= 1) {
        if (threadIdx.x < st) red[threadIdx.x] += red[threadIdx.x + st];
        __syncthreads();
    }
    float scale = rsqrtf(red[0] / (float)D_INNER + EPS);
    for (int c = threadIdx.x; c < D_INNER; c += blockDim.x)
        orr[c] = vbuf[c] * scale * w[c];
}

// ---------------- SwiGLU combine ----------------
__global__ void swiglu_kernel(const float* __restrict__ g, const float* __restrict__ u,
                              float* __restrict__ o) {
    long idx = (long)blockIdx.x * blockDim.x + threadIdx.x;
    if (idx >= (long)TOK * INTER) return;
    float gv = g[idx];
    o[idx] = (gv / (1.f + expf(-gv))) * u[idx];
}

// ---------------- Launch ----------------
#define GEMM_SMEM (2 * STG * ST_SZ * (int)sizeof(float))   // 61440 B

extern "C" void kernel_launch(void* const* d_in, const int* in_sizes, int n_in,
                              void* d_out, int out_size) {
    const float* hidden     = (const float*)d_in[0];
    const float* norm_w     = (const float*)d_in[1];
    const float* in_proj_w  = (const float*)d_in[2];
    const float* conv_w     = (const float*)d_in[3];
    const float* conv_b     = (const float*)d_in[4];
    const float* dt_bias    = (const float*)d_in[5];
    const float* A_log      = (const float*)d_in[6];
    const float* Dp         = (const float*)d_in[7];
    const float* ssm_norm_w = (const float*)d_in[8];
    const float* out_proj_w = (const float*)d_in[9];
    const float* post_norm_w= (const float*)d_in[10];
    const float* gate_w     = (const float*)d_in[11];
    const float* up_w       = (const float*)d_in[12];
    const float* down_w     = (const float*)d_in[13];
    float* out = (float*)d_out;

    float *h, *zx, *xbc, *dtb, *y, *yn, *x1, *h2, *gt, *up, *it;
    cudaGetSymbolAddress((void**)&h,   g_h);
    cudaGetSymbolAddress((void**)&zx,  g_zx);
    cudaGetSymbolAddress((void**)&xbc, g_xbc);
    cudaGetSymbolAddress((void**)&dtb, g_dt);
    cudaGetSymbolAddress((void**)&y,   g_y);
    cudaGetSymbolAddress((void**)&yn,  g_yn);
    cudaGetSymbolAddress((void**)&x1,  g_x1);
    cudaGetSymbolAddress((void**)&h2,  g_h2);
    cudaGetSymbolAddress((void**)&gt,  g_gate);
    cudaGetSymbolAddress((void**)&up,  g_up);
    cudaGetSymbolAddress((void**)&it,  g_inter);

    static bool attr_set = false;
    if (!attr_set) {
        cudaFuncSetAttribute(gemm_tf32, cudaFuncAttributeMaxDynamicSharedMemorySize, GEMM_SMEM);
        attr_set = true;
    }

    // 1) pre-norm
    rmsnorm_kernel<<<TOK, 256>>>(hidden, norm_w, h, D_MODEL);

    // 2) in_proj
    {
        dim3 grid((D_IN_PROJ + BN - 1) / BN, TOK / BM);
        gemm_tf32<<<grid, 256, GEMM_SMEM>>>(h, in_proj_w, nullptr, zx, TOK, D_IN_PROJ, D_MODEL);
    }

    // 3) causal conv + silu
    {
        long total = (long)TOK * CONV_DIM;
        conv_silu_kernel<<<(unsigned)((total + 255) / 256), 256>>>(zx, conv_w, conv_b, xbc);
    }

    // 4) dt softplus
    dt_softplus_kernel<<<(TOK * NHEADS + 255) / 256, 256>>>(zx, dt_bias, dtb);

    // 5) SSM scan
    scan_kernel<<<BATCH * NHEADS, 256>>>(xbc, dtb, A_log, Dp, y);

    // 6) gated rmsnorm
    gated_rmsnorm_kernel<<<TOK, 256>>>(y, zx, ssm_norm_w, yn);

    // 7) out_proj + residual
    {
        dim3 grid(D_MODEL / BN, TOK / BM);
        gemm_tf32<<<grid, 256, GEMM_SMEM>>>(yn, out_proj_w, hidden, x1, TOK, D_MODEL, D_INNER);
    }

    // 8) post-norm
    rmsnorm_kernel<<<TOK, 256>>>(x1, post_norm_w, h2, D_MODEL);

    // 9) gate & up GEMMs
    {
        dim3 grid((INTER + BN - 1) / BN, TOK / BM);
        gemm_tf32<<<grid, 256, GEMM_SMEM>>>(h2, gate_w, nullptr, gt, TOK, INTER, D_MODEL);
        gemm_tf32<<<grid, 256, GEMM_SMEM>>>(h2, up_w,   nullptr, up, TOK, INTER, D_MODEL);
    }

    // 10) swiglu
    {
        long total = (long)TOK * INTER;
        swiglu_kernel<<<(unsigned)((total + 255) / 256), 256>>>(gt, up, it);
    }

    // 11) down proj + residual -> out
    {
        dim3 grid(D_MODEL / BN, TOK / BM);
        gemm_tf32<<<grid, 256, GEMM_SMEM>>>(it, down_w, x1, out, TOK, D_MODEL, INTER);
    }
}